// round 8
// baseline (speedup 1.0000x reference)
#include <cuda_runtime.h>

#define BATCH   4
#define NPTS    8192
#define KNN     8
#define TILE    1024
#define QBLK    32       // queries per block
#define THREADS 128      // 4 threads per query (candidate split)
#define NSPLIT  4

typedef unsigned long long u64;

__device__ float4 g_pred4[BATCH * NPTS];
__device__ float4 g_targ4[BATCH * NPTS];
__device__ float g_sx[2 * BATCH * NPTS];
__device__ float g_sy[2 * BATCH * NPTS];
__device__ float g_sz[2 * BATCH * NPTS];
__device__ float g_sw[2 * BATCH * NPTS];

__device__ __forceinline__ u64 pack2(float lo, float hi) {
    u64 r;
    asm("mov.b64 %0, {%1, %2};" : "=l"(r) : "f"(lo), "f"(hi));
    return r;
}
__device__ __forceinline__ float lo32(u64 v) { return __uint_as_float((unsigned)v); }
__device__ __forceinline__ float hi32(u64 v) { return __uint_as_float((unsigned)(v >> 32)); }
__device__ __forceinline__ u64 ffma2(u64 a, u64 b, u64 c) {
    u64 d;
    asm("fma.rn.f32x2 %0, %1, %2, %3;" : "=l"(d) : "l"(a), "l"(b), "l"(c));
    return d;
}

__global__ void prep_kernel(const float* __restrict__ src,
                            const float* __restrict__ tgt,
                            const float* __restrict__ flow) {
    int i = blockIdx.x * blockDim.x + threadIdx.x;
    if (i >= BATCH * NPTS) return;
    float px = src[3 * i + 0] + flow[3 * i + 0];
    float py = src[3 * i + 1] + flow[3 * i + 1];
    float pz = src[3 * i + 2] + flow[3 * i + 2];
    float pw = px * px + py * py + pz * pz;
    g_pred4[i] = make_float4(px, py, pz, pw);
    g_sx[i] = px; g_sy[i] = py; g_sz[i] = pz; g_sw[i] = pw;

    float tx = tgt[3 * i + 0], ty = tgt[3 * i + 1], tz = tgt[3 * i + 2];
    float tw = tx * tx + ty * ty + tz * tz;
    g_targ4[i] = make_float4(tx, ty, tz, tw);
    int j = BATCH * NPTS + i;
    g_sx[j] = tx; g_sy[j] = ty; g_sz[j] = tz; g_sw[j] = tw;
}

// Branchless sorted-descending insert (caller guarantees val < h[0])
#define INSERT8(h, val)                          \
    do {                                         \
        float _v = (val);                        \
        _Pragma("unroll")                        \
        for (int _i = 0; _i < KNN - 1; ++_i) {   \
            float _nx = h[_i + 1];               \
            h[_i] = fmaxf(_v, _nx);              \
            _v = fminf(_v, _nx);                 \
        }                                        \
        h[KNN - 1] = _v;                         \
    } while (0)

#define TRYINS(h, val) do { if ((val) < h[0]) INSERT8(h, (val)); } while (0)

__global__ void __launch_bounds__(THREADS, 9)
chamfer_kernel(float* __restrict__ out) {
    // x @ 0, y @ TILE, z @ 2*TILE, w @ 3*TILE
    __shared__ __align__(16) float sm[4 * TILE];
    __shared__ float m8[NSPLIT - 1][QBLK][KNN];

    const int b   = blockIdx.y;
    const int dir = blockIdx.z;
    const float4* q4 = (dir == 0 ? g_pred4 : g_targ4) + b * NPTS;
    const int coff = (dir == 0 ? 1 : 0) * BATCH * NPTS + b * NPTS;

    const int qt   = threadIdx.x & (QBLK - 1);   // = lane id
    const int part = threadIdx.x >> 5;           // warp-uniform, 0..3
    const int qi   = blockIdx.x * QBLK + qt;
    const float4 q = q4[qi];
    const u64 ax2 = pack2(-2.0f * q.x, -2.0f * q.x);
    const u64 ay2 = pack2(-2.0f * q.y, -2.0f * q.y);
    const u64 az2 = pack2(-2.0f * q.z, -2.0f * q.z);

    float h[KNN];
#pragma unroll
    for (int i = 0; i < KNN; ++i) h[i] = 1.0e30f;

    for (int t0 = 0; t0 < NPTS; t0 += TILE) {
        __syncthreads();
#pragma unroll
        for (int l = threadIdx.x; l < TILE / 4; l += THREADS) {
            ((float4*)sm)[l]              = ((const float4*)(g_sx + coff + t0))[l];
            ((float4*)(sm + TILE))[l]     = ((const float4*)(g_sy + coff + t0))[l];
            ((float4*)(sm + 2 * TILE))[l] = ((const float4*)(g_sz + coff + t0))[l];
            ((float4*)(sm + 3 * TILE))[l] = ((const float4*)(g_sw + coff + t0))[l];
        }
        __syncthreads();

        // Each warp (part) handles interleaved 4-candidate groups, stride 16
        const float* base = sm + 4 * part;
#pragma unroll 4
        for (int j = 0; j < TILE; j += 16) {
            const ulonglong2 X = *(const ulonglong2*)(base + j);
            const ulonglong2 Y = *(const ulonglong2*)(base + j + TILE);
            const ulonglong2 Z = *(const ulonglong2*)(base + j + 2 * TILE);
            const ulonglong2 W = *(const ulonglong2*)(base + j + 3 * TILE);

            // t = |c|^2 - 2 q.c  (ranking key; |q|^2 re-added at the end)
            u64 t01 = ffma2(ax2, X.x, ffma2(ay2, Y.x, ffma2(az2, Z.x, W.x)));
            u64 t23 = ffma2(ax2, X.y, ffma2(ay2, Y.y, ffma2(az2, Z.y, W.y)));

            float f0 = lo32(t01), f1 = hi32(t01);
            float f2 = lo32(t23), f3 = hi32(t23);

            // Two independent pair-guard regions (no nesting)
            if (fminf(f0, f1) < h[0]) { TRYINS(h, f0); TRYINS(h, f1); }
            if (fminf(f2, f3) < h[0]) { TRYINS(h, f2); TRYINS(h, f3); }
        }
    }

    // Merge the 4 parts' top-8 lists (parts 1..3 -> smem, part 0 merges)
    if (part) {
#pragma unroll
        for (int i = 0; i < KNN; ++i) m8[part - 1][qt][i] = h[i];
    }
    __syncthreads();
    if (part == 0) {
#pragma unroll
        for (int p = 0; p < NSPLIT - 1; ++p)
#pragma unroll
            for (int i = 0; i < KNN; ++i)
                TRYINS(h, m8[p][qt][i]);

        float s = 0.0f;
#pragma unroll
        for (int i = 0; i < KNN; ++i)
            s += sqrtf(fmaxf(q.w + h[i], 0.0f));

        // warp 0 holds all QBLK query sums: shuffle-reduce
#pragma unroll
        for (int off = 16; off > 0; off >>= 1)
            s += __shfl_down_sync(0xFFFFFFFFu, s, off);
        if (qt == 0)
            atomicAdd(out, s * (1.0f / (KNN * BATCH * NPTS)));
    }
}

extern "C" void kernel_launch(void* const* d_in, const int* in_sizes, int n_in,
                              void* d_out, int out_size) {
    const float* src  = (const float*)d_in[0];
    const float* tgt  = (const float*)d_in[1];
    const float* flow = (const float*)d_in[2];
    float* out = (float*)d_out;

    cudaMemsetAsync(out, 0, sizeof(float), 0);

    int npts = BATCH * NPTS;
    prep_kernel<<<(npts + 255) / 256, 256>>>(src, tgt, flow);

    dim3 grid(NPTS / QBLK, BATCH, 2);
    chamfer_kernel<<<grid, THREADS>>>(out);
}

// round 9
// speedup vs baseline: 1.2174x; 1.2174x over previous
#include <cuda_runtime.h>

#define BATCH   4
#define NPTS    8192
#define KNN     8
#define TILE    1024
#define QBLK    64       // queries per block
#define THREADS 128      // 2 threads per query (candidate split)

typedef unsigned long long u64;

__device__ float4 g_pred4[BATCH * NPTS];
__device__ float4 g_targ4[BATCH * NPTS];
__device__ float4 g_pred4s[BATCH * NPTS];   // Morton-sorted queries
__device__ float4 g_targ4s[BATCH * NPTS];
__device__ unsigned g_key[2][BATCH * NPTS]; // (morton18 << 13) | idx13
__device__ float g_sx[2 * BATCH * NPTS];
__device__ float g_sy[2 * BATCH * NPTS];
__device__ float g_sz[2 * BATCH * NPTS];
__device__ float g_sw[2 * BATCH * NPTS];

__device__ __forceinline__ u64 pack2(float lo, float hi) {
    u64 r;
    asm("mov.b64 %0, {%1, %2};" : "=l"(r) : "f"(lo), "f"(hi));
    return r;
}
__device__ __forceinline__ float lo32(u64 v) { return __uint_as_float((unsigned)v); }
__device__ __forceinline__ float hi32(u64 v) { return __uint_as_float((unsigned)(v >> 32)); }
__device__ __forceinline__ u64 ffma2(u64 a, u64 b, u64 c) {
    u64 d;
    asm("fma.rn.f32x2 %0, %1, %2, %3;" : "=l"(d) : "l"(a), "l"(b), "l"(c));
    return d;
}

__device__ __forceinline__ unsigned morton18(float x, float y, float z) {
    int ax = (int)((x + 4.0f) * 8.0f); ax = ax < 0 ? 0 : (ax > 63 ? 63 : ax);
    int ay = (int)((y + 4.0f) * 8.0f); ay = ay < 0 ? 0 : (ay > 63 ? 63 : ay);
    int az = (int)((z + 4.0f) * 8.0f); az = az < 0 ? 0 : (az > 63 ? 63 : az);
    unsigned m = 0;
#pragma unroll
    for (int bit = 0; bit < 6; ++bit) {
        m |= ((unsigned)((ax >> bit) & 1)) << (3 * bit + 2);
        m |= ((unsigned)((ay >> bit) & 1)) << (3 * bit + 1);
        m |= ((unsigned)((az >> bit) & 1)) << (3 * bit + 0);
    }
    return m;
}

__global__ void prep_kernel(const float* __restrict__ src,
                            const float* __restrict__ tgt,
                            const float* __restrict__ flow) {
    int i = blockIdx.x * blockDim.x + threadIdx.x;
    if (i >= BATCH * NPTS) return;
    int li = i & (NPTS - 1);

    float px = src[3 * i + 0] + flow[3 * i + 0];
    float py = src[3 * i + 1] + flow[3 * i + 1];
    float pz = src[3 * i + 2] + flow[3 * i + 2];
    float pw = px * px + py * py + pz * pz;
    g_pred4[i] = make_float4(px, py, pz, pw);
    g_sx[i] = px; g_sy[i] = py; g_sz[i] = pz; g_sw[i] = pw;
    g_key[0][i] = (morton18(px, py, pz) << 13) | (unsigned)li;

    float tx = tgt[3 * i + 0], ty = tgt[3 * i + 1], tz = tgt[3 * i + 2];
    float tw = tx * tx + ty * ty + tz * tz;
    g_targ4[i] = make_float4(tx, ty, tz, tw);
    int j = BATCH * NPTS + i;
    g_sx[j] = tx; g_sy[j] = ty; g_sz[j] = tz; g_sw[j] = tw;
    g_key[1][i] = (morton18(tx, ty, tz) << 13) | (unsigned)li;
}

// Bitonic sort of 8192 packed keys in smem, then gather-permute queries.
// grid = 8 blocks: blockIdx.x = set * BATCH + batch
__global__ void __launch_bounds__(1024)
sort_kernel() {
    __shared__ unsigned sk[NPTS];
    const int set = blockIdx.x >> 2;       // 0 = pred, 1 = targ
    const int b   = blockIdx.x & 3;
    const int tid = threadIdx.x;

    for (int i = tid; i < NPTS; i += 1024)
        sk[i] = g_key[set][b * NPTS + i];

    for (int k = 2; k <= NPTS; k <<= 1) {
        for (int j = k >> 1; j > 0; j >>= 1) {
            __syncthreads();
            for (int i = tid; i < NPTS; i += 1024) {
                int ixj = i ^ j;
                if (ixj > i) {
                    unsigned a = sk[i], c = sk[ixj];
                    bool up = ((i & k) == 0);
                    if ((a > c) == up) { sk[i] = c; sk[ixj] = a; }
                }
            }
        }
    }
    __syncthreads();

    const float4* src4 = (set == 0 ? g_pred4 : g_targ4) + b * NPTS;
    float4* dst4 = (set == 0 ? g_pred4s : g_targ4s) + b * NPTS;
    for (int i = tid; i < NPTS; i += 1024)
        dst4[i] = src4[sk[i] & (NPTS - 1)];
}

// Branchless sorted-descending insert (caller guarantees val < h[0])
#define INSERT8(h, val)                          \
    do {                                         \
        float _v = (val);                        \
        _Pragma("unroll")                        \
        for (int _i = 0; _i < KNN - 1; ++_i) {   \
            float _nx = h[_i + 1];               \
            h[_i] = fmaxf(_v, _nx);              \
            _v = fminf(_v, _nx);                 \
        }                                        \
        h[KNN - 1] = _v;                         \
    } while (0)

#define TRYINS(h, val) do { if ((val) < h[0]) INSERT8(h, (val)); } while (0)

__global__ void __launch_bounds__(THREADS, 8)
chamfer_kernel(float* __restrict__ out) {
    // x @ 0, y @ TILE, z @ 2*TILE, w @ 3*TILE
    __shared__ __align__(16) float sm[4 * TILE];
    __shared__ float m8[QBLK][KNN];
    __shared__ float red[QBLK];

    const int b   = blockIdx.y;
    const int dir = blockIdx.z;
    const float4* q4 = (dir == 0 ? g_pred4s : g_targ4s) + b * NPTS;
    const int coff = (dir == 0 ? 1 : 0) * BATCH * NPTS + b * NPTS;

    const int qt   = threadIdx.x & (QBLK - 1);
    const int half = threadIdx.x >> 6;       // warp-uniform
    const int qi   = blockIdx.x * QBLK + qt;
    const float4 q = q4[qi];
    const u64 ax2 = pack2(-2.0f * q.x, -2.0f * q.x);
    const u64 ay2 = pack2(-2.0f * q.y, -2.0f * q.y);
    const u64 az2 = pack2(-2.0f * q.z, -2.0f * q.z);

    float h[KNN];
#pragma unroll
    for (int i = 0; i < KNN; ++i) h[i] = 1.0e30f;

    for (int t0 = 0; t0 < NPTS; t0 += TILE) {
        __syncthreads();
#pragma unroll
        for (int l = threadIdx.x; l < TILE / 4; l += THREADS) {
            ((float4*)sm)[l]              = ((const float4*)(g_sx + coff + t0))[l];
            ((float4*)(sm + TILE))[l]     = ((const float4*)(g_sy + coff + t0))[l];
            ((float4*)(sm + 2 * TILE))[l] = ((const float4*)(g_sz + coff + t0))[l];
            ((float4*)(sm + 3 * TILE))[l] = ((const float4*)(g_sw + coff + t0))[l];
        }
        __syncthreads();

        // Each thread: interleaved 4-candidate groups, stride 8
        const float* base = sm + 4 * half;
#pragma unroll 4
        for (int j = 0; j < TILE; j += 8) {
            const ulonglong2 X = *(const ulonglong2*)(base + j);
            const ulonglong2 Y = *(const ulonglong2*)(base + j + TILE);
            const ulonglong2 Z = *(const ulonglong2*)(base + j + 2 * TILE);
            const ulonglong2 W = *(const ulonglong2*)(base + j + 3 * TILE);

            // t = |c|^2 - 2 q.c  (ranking key; |q|^2 re-added at the end)
            u64 t01 = ffma2(ax2, X.x, ffma2(ay2, Y.x, ffma2(az2, Z.x, W.x)));
            u64 t23 = ffma2(ax2, X.y, ffma2(ay2, Y.y, ffma2(az2, Z.y, W.y)));

            float f0 = lo32(t01), f1 = hi32(t01);
            float f2 = lo32(t23), f3 = hi32(t23);

            float m = fminf(fminf(f0, f1), fminf(f2, f3));
            if (m < h[0]) {
                TRYINS(h, f0); TRYINS(h, f1);
                TRYINS(h, f2); TRYINS(h, f3);
            }
        }
    }

    // Merge the two halves' top-8 lists
    if (half) {
#pragma unroll
        for (int i = 0; i < KNN; ++i) m8[qt][i] = h[i];
    }
    __syncthreads();
    if (!half) {
#pragma unroll
        for (int i = 0; i < KNN; ++i)
            TRYINS(h, m8[qt][i]);
        float s = 0.0f;
#pragma unroll
        for (int i = 0; i < KNN; ++i)
            s += sqrtf(fmaxf(q.w + h[i], 0.0f));
        red[qt] = s;
    }
    __syncthreads();
#pragma unroll
    for (int off = QBLK / 2; off > 0; off >>= 1) {
        if (threadIdx.x < off) red[threadIdx.x] += red[threadIdx.x + off];
        __syncthreads();
    }
    if (threadIdx.x == 0)
        atomicAdd(out, red[0] * (1.0f / (KNN * BATCH * NPTS)));
}

extern "C" void kernel_launch(void* const* d_in, const int* in_sizes, int n_in,
                              void* d_out, int out_size) {
    const float* src  = (const float*)d_in[0];
    const float* tgt  = (const float*)d_in[1];
    const float* flow = (const float*)d_in[2];
    float* out = (float*)d_out;

    cudaMemsetAsync(out, 0, sizeof(float), 0);

    int npts = BATCH * NPTS;
    prep_kernel<<<(npts + 255) / 256, 256>>>(src, tgt, flow);
    sort_kernel<<<8, 1024>>>();

    dim3 grid(NPTS / QBLK, BATCH, 2);
    chamfer_kernel<<<grid, THREADS>>>(out);
}